// round 1
// baseline (speedup 1.0000x reference)
#include <cuda_runtime.h>

#define NB 4
#define NN 2048
#define NC 256
#define NH 4
#define HD 64

// ---- scratch (allocation-free: __device__ globals) ----
__device__ float g_X[NB*NN*NC];                 // lrelu(node@W_lin+b)
__device__ float g_q[NB*NN*NC];                 // lrelu(node@W_q)
__device__ float g_k[NB*NN*NC];                 // lrelu(node@W_k)
__device__ float g_Y[NB*NN*NC];                 // aggregated pre-LN
__device__ float g_dis[NB*NH*NN];               // deg^-1/2
__device__ float g_W[(size_t)NB*NH*NN*NN];      // adj * sigmoid(qk/8)  (256MB)

// ============================================================
// K1: C[8192,256] = lrelu(A[8192,256] @ W[256,256] (+ bias))
// 64x64 tile, BK=16, 256 threads, 4x4 micro-tile
// ============================================================
__global__ __launch_bounds__(256) void k1_gemm(const float* __restrict__ A,
                                               const float* __restrict__ Wm,
                                               const float* __restrict__ bias,
                                               int sel) {
    __shared__ float As[16][68];   // [k][m]
    __shared__ float Bs[16][68];   // [k][n]
    const int bx = blockIdx.x, by = blockIdx.y;
    const int tid = threadIdx.x;
    const int tx = tid & 15, ty = tid >> 4;
    const int M0 = by * 64, N0 = bx * 64;
    float acc[4][4] = {};
    for (int k0 = 0; k0 < 256; k0 += 16) {
        {   // A tile -> transposed smem
            int r = tid >> 2, c = (tid & 3) * 4;
            float4 v = *(const float4*)(A + (size_t)(M0 + r) * 256 + k0 + c);
            As[c+0][r] = v.x; As[c+1][r] = v.y; As[c+2][r] = v.z; As[c+3][r] = v.w;
        }
        {   // W tile
            int r = tid >> 4, c = (tid & 15) * 4;
            float4 v = *(const float4*)(Wm + (size_t)(k0 + r) * 256 + N0 + c);
            *(float4*)&Bs[r][c] = v;
        }
        __syncthreads();
        #pragma unroll
        for (int kk = 0; kk < 16; kk++) {
            float4 a4 = *(const float4*)&As[kk][ty*4];
            float4 b4 = *(const float4*)&Bs[kk][tx*4];
            float a[4] = {a4.x, a4.y, a4.z, a4.w};
            float b[4] = {b4.x, b4.y, b4.z, b4.w};
            #pragma unroll
            for (int i = 0; i < 4; i++)
                #pragma unroll
                for (int j = 0; j < 4; j++) acc[i][j] += a[i] * b[j];
        }
        __syncthreads();
    }
    float* out = (sel == 0) ? g_X : ((sel == 1) ? g_q : g_k);
    #pragma unroll
    for (int i = 0; i < 4; i++) {
        int row = M0 + ty*4 + i;
        #pragma unroll
        for (int j = 0; j < 4; j++) {
            int col = N0 + tx*4 + j;
            float v = acc[i][j];
            if (bias) v += bias[col];
            v = (v >= 0.f) ? v : 0.01f * v;
            out[(size_t)row * 256 + col] = v;
        }
    }
}

// a * sigmoid(s/8) with fast exp/div (rel err ~1e-6, well under 1e-3 budget)
__device__ __forceinline__ float sigw(float a, float s) {
    float e = __expf(-0.125f * s);
    return __fdividef(a, 1.f + e);
}

// ============================================================
// K2: per (b,h,x-tile64): W[b,h,x,y] = adj*sigmoid(q.k/8), dis = rsqrt(rowsum)
// ============================================================
__global__ __launch_bounds__(256) void k2_att(const float* __restrict__ adj) {
    const int xt = blockIdx.x, h = blockIdx.y, b = blockIdx.z;
    const int x0 = xt * 64;
    __shared__ float qs[64][68];   // [d][x]
    __shared__ float ks[64][68];   // [d][y]
    const int tid = threadIdx.x;
    const int tx = tid & 15, ty = tid >> 4;
    {   // q tile transposed (loaded once per block)
        int x = tid >> 2, db = (tid & 3) * 16;
        const float* src = g_q + ((size_t)(b*NN + x0 + x)) * NC + h*HD + db;
        #pragma unroll
        for (int u = 0; u < 4; u++) {
            float4 v = *(const float4*)(src + u*4);
            qs[db+u*4+0][x] = v.x; qs[db+u*4+1][x] = v.y;
            qs[db+u*4+2][x] = v.z; qs[db+u*4+3][x] = v.w;
        }
    }
    float dsum[4] = {0.f, 0.f, 0.f, 0.f};
    float* Wbase = g_W + ((size_t)(b*NH + h)) * NN * NN;
    for (int yt = 0; yt < NN/64; yt++) {
        const int y0 = yt * 64;
        __syncthreads();
        {   // k tile transposed
            int y = tid >> 2, db = (tid & 3) * 16;
            const float* src = g_k + ((size_t)(b*NN + y0 + y)) * NC + h*HD + db;
            #pragma unroll
            for (int u = 0; u < 4; u++) {
                float4 v = *(const float4*)(src + u*4);
                ks[db+u*4+0][y] = v.x; ks[db+u*4+1][y] = v.y;
                ks[db+u*4+2][y] = v.z; ks[db+u*4+3][y] = v.w;
            }
        }
        __syncthreads();
        float acc[4][4] = {};
        #pragma unroll 8
        for (int d = 0; d < 64; d++) {
            float4 a4 = *(const float4*)&qs[d][ty*4];
            float4 b4 = *(const float4*)&ks[d][tx*4];
            float a[4] = {a4.x, a4.y, a4.z, a4.w};
            float bb[4] = {b4.x, b4.y, b4.z, b4.w};
            #pragma unroll
            for (int i = 0; i < 4; i++)
                #pragma unroll
                for (int j = 0; j < 4; j++) acc[i][j] += a[i] * bb[j];
        }
        #pragma unroll
        for (int i = 0; i < 4; i++) {
            int x = x0 + ty*4 + i;
            float4 a = *(const float4*)(adj + ((size_t)(b*NN + x)) * NN + y0 + tx*4);
            float4 w;
            w.x = sigw(a.x, acc[i][0]);
            w.y = sigw(a.y, acc[i][1]);
            w.z = sigw(a.z, acc[i][2]);
            w.w = sigw(a.w, acc[i][3]);
            *(float4*)(Wbase + (size_t)x * NN + y0 + tx*4) = w;
            dsum[i] += (w.x + w.y) + (w.z + w.w);
        }
    }
    // reduce row sums across the 16 lanes sharing each row (lanes contiguous)
    #pragma unroll
    for (int i = 0; i < 4; i++) {
        float v = dsum[i];
        #pragma unroll
        for (int o = 8; o; o >>= 1) v += __shfl_xor_sync(0xffffffffu, v, o);
        if (tx == 0) {
            int x = x0 + ty*4 + i;
            g_dis[(b*NH + h)*NN + x] = (v > 0.f) ? rsqrtf(v) : 0.f;
        }
    }
}

// ============================================================
// K4: Y[b,x,h*64+d] = dis_x * sum_y W[b,h,x,y]*dis_y*X[b,y,h*64+d]
// ============================================================
__global__ __launch_bounds__(256) void k4_agg() {
    const int xt = blockIdx.x, h = blockIdx.y, b = blockIdx.z;
    const int x0 = xt * 64;
    __shared__ float Wst[64][68];  // [y][x]
    __shared__ float Xs[64][68];   // [y][d] (pre-scaled by dis_y)
    const int tid = threadIdx.x;
    const int tx = tid & 15, ty = tid >> 4;
    const float* Wbase = g_W + ((size_t)(b*NH + h)) * NN * NN;
    const float* disb  = g_dis + (b*NH + h) * NN;
    float acc[4][4] = {};
    for (int yt = 0; yt < NN/64; yt++) {
        const int y0 = yt * 64;
        __syncthreads();
        {   // W tile transposed
            int x = tid >> 2, yb = (tid & 3) * 16;
            const float* src = Wbase + (size_t)(x0 + x) * NN + y0 + yb;
            #pragma unroll
            for (int u = 0; u < 4; u++) {
                float4 v = *(const float4*)(src + u*4);
                Wst[yb+u*4+0][x] = v.x; Wst[yb+u*4+1][x] = v.y;
                Wst[yb+u*4+2][x] = v.z; Wst[yb+u*4+3][x] = v.w;
            }
        }
        {   // X tile, scaled by dis_y at load
            int y = tid >> 2, db = (tid & 3) * 16;
            float dy = disb[y0 + y];
            const float* src = g_X + ((size_t)(b*NN + y0 + y)) * NC + h*HD + db;
            #pragma unroll
            for (int u = 0; u < 4; u++) {
                float4 v = *(const float4*)(src + u*4);
                float4 sv = make_float4(v.x*dy, v.y*dy, v.z*dy, v.w*dy);
                *(float4*)&Xs[y][db + u*4] = sv;
            }
        }
        __syncthreads();
        #pragma unroll 8
        for (int yy = 0; yy < 64; yy++) {
            float4 a4 = *(const float4*)&Wst[yy][ty*4];
            float4 b4 = *(const float4*)&Xs[yy][tx*4];
            float a[4] = {a4.x, a4.y, a4.z, a4.w};
            float bb[4] = {b4.x, b4.y, b4.z, b4.w};
            #pragma unroll
            for (int i = 0; i < 4; i++)
                #pragma unroll
                for (int j = 0; j < 4; j++) acc[i][j] += a[i] * bb[j];
        }
    }
    #pragma unroll
    for (int i = 0; i < 4; i++) {
        int x = x0 + ty*4 + i;
        float dx = disb[x];
        float4 o = make_float4(acc[i][0]*dx, acc[i][1]*dx, acc[i][2]*dx, acc[i][3]*dx);
        *(float4*)(g_Y + ((size_t)(b*NN + x)) * NC + h*HD + tx*4) = o;
    }
}

// ============================================================
// K5: LayerNorm over last dim (256), warp per row
// ============================================================
__global__ __launch_bounds__(256) void k5_ln(const float* __restrict__ g,
                                             const float* __restrict__ bta,
                                             float* __restrict__ out) {
    int gw = (blockIdx.x * 256 + threadIdx.x) >> 5;
    int lane = threadIdx.x & 31;
    if (gw >= NB*NN) return;
    const float* row = g_Y + (size_t)gw * NC;
    float4 v0 = *(const float4*)(row + lane*8);
    float4 v1 = *(const float4*)(row + lane*8 + 4);
    float s  = (v0.x+v0.y) + (v0.z+v0.w) + (v1.x+v1.y) + (v1.z+v1.w);
    float s2 = v0.x*v0.x + v0.y*v0.y + v0.z*v0.z + v0.w*v0.w
             + v1.x*v1.x + v1.y*v1.y + v1.z*v1.z + v1.w*v1.w;
    #pragma unroll
    for (int o = 16; o; o >>= 1) {
        s  += __shfl_xor_sync(0xffffffffu, s,  o);
        s2 += __shfl_xor_sync(0xffffffffu, s2, o);
    }
    float mu  = s * (1.f/NC);
    float var = s2 * (1.f/NC) - mu * mu;
    float inv = rsqrtf(var + 1e-5f);
    int c = lane * 8;
    float4 g0 = *(const float4*)(g + c),   g1 = *(const float4*)(g + c + 4);
    float4 b0 = *(const float4*)(bta + c), b1 = *(const float4*)(bta + c + 4);
    float4 o0, o1;
    o0.x = (v0.x-mu)*inv*g0.x + b0.x;  o0.y = (v0.y-mu)*inv*g0.y + b0.y;
    o0.z = (v0.z-mu)*inv*g0.z + b0.z;  o0.w = (v0.w-mu)*inv*g0.w + b0.w;
    o1.x = (v1.x-mu)*inv*g1.x + b1.x;  o1.y = (v1.y-mu)*inv*g1.y + b1.y;
    o1.z = (v1.z-mu)*inv*g1.z + b1.z;  o1.w = (v1.w-mu)*inv*g1.w + b1.w;
    *(float4*)(out + (size_t)gw*NC + c)     = o0;
    *(float4*)(out + (size_t)gw*NC + c + 4) = o1;
}

extern "C" void kernel_launch(void* const* d_in, const int* in_sizes, int n_in,
                              void* d_out, int out_size) {
    const float* node = (const float*)d_in[0];
    const float* adj  = (const float*)d_in[1];
    const float* Wlin = (const float*)d_in[2];
    const float* blin = (const float*)d_in[3];
    const float* Wq   = (const float*)d_in[4];
    const float* Wk   = (const float*)d_in[5];
    const float* lng  = (const float*)d_in[6];
    const float* lnb  = (const float*)d_in[7];
    float* out = (float*)d_out;

    dim3 g1(256/64, (NB*NN)/64);            // (4, 128)
    k1_gemm<<<g1, 256>>>(node, Wlin, blin, 0);
    k1_gemm<<<g1, 256>>>(node, Wq, nullptr, 1);
    k1_gemm<<<g1, 256>>>(node, Wk, nullptr, 2);

    dim3 g2(NN/64, NH, NB);                 // (32, 4, 4)
    k2_att<<<g2, 256>>>(adj);
    k4_agg<<<g2, 256>>>();

    k5_ln<<<(NB*NN)/8, 256>>>(lng, lnb, out);
}

// round 2
// speedup vs baseline: 1.0465x; 1.0465x over previous
#include <cuda_runtime.h>

#define NB 4
#define NN 2048
#define NC 256
#define NH 4
#define HD 64

// ---- scratch (allocation-free: __device__ globals) ----
__device__ float g_X[NB*NN*NC];
__device__ float g_q[NB*NN*NC];
__device__ float g_k[NB*NN*NC];
__device__ float g_Y[NB*NN*NC];
__device__ float g_dis[NB*NH*NN];
__device__ float g_W[(size_t)NB*NH*NN*NN];      // 256MB

// ============================================================
// K1: out = lrelu(A[8192,256] @ W[256,256] (+bias))
// 128x128 tile, BK=16, 256 threads, 8x8 micro-tile, z selects weight
// ============================================================
__global__ __launch_bounds__(256) void k1_gemm(const float* __restrict__ A,
                                               const float* __restrict__ W0,
                                               const float* __restrict__ W1,
                                               const float* __restrict__ W2,
                                               const float* __restrict__ bias) {
    const int z = blockIdx.z;
    const float* Wm = (z == 0) ? W0 : ((z == 1) ? W1 : W2);
    float* out = (z == 0) ? g_X : ((z == 1) ? g_q : g_k);
    __shared__ float As[16][136];   // [k][m]
    __shared__ float Bs[16][136];   // [k][n]
    const int tid = threadIdx.x;
    const int tx = tid & 15, ty = tid >> 4;
    const int M0 = blockIdx.y * 128, N0 = blockIdx.x * 128;
    float acc[8][8] = {};
    for (int k0 = 0; k0 < 256; k0 += 16) {
        __syncthreads();
        {   // A tile 128x16 -> transposed
            int f = tid & 3;
            #pragma unroll
            for (int p = 0; p < 2; p++) {
                int r = p*64 + (tid >> 2);
                float4 v = *(const float4*)(A + (size_t)(M0 + r)*NC + k0 + f*4);
                As[f*4+0][r] = v.x; As[f*4+1][r] = v.y;
                As[f*4+2][r] = v.z; As[f*4+3][r] = v.w;
            }
        }
        {   // B tile 16x128
            int r = tid >> 4, c = (tid & 15) * 8;
            const float* src = Wm + (size_t)(k0 + r)*NC + N0 + c;
            *(float4*)&Bs[r][c]   = *(const float4*)(src);
            *(float4*)&Bs[r][c+4] = *(const float4*)(src + 4);
        }
        __syncthreads();
        #pragma unroll
        for (int kk = 0; kk < 16; kk++) {
            float a[8], bv[8];
            *(float4*)(a)    = *(const float4*)&As[kk][ty*8];
            *(float4*)(a+4)  = *(const float4*)&As[kk][ty*8+4];
            *(float4*)(bv)   = *(const float4*)&Bs[kk][tx*8];
            *(float4*)(bv+4) = *(const float4*)&Bs[kk][tx*8+4];
            #pragma unroll
            for (int i = 0; i < 8; i++)
                #pragma unroll
                for (int j = 0; j < 8; j++) acc[i][j] += a[i] * bv[j];
        }
    }
    #pragma unroll
    for (int i = 0; i < 8; i++) {
        int row = M0 + ty*8 + i;
        float o[8];
        #pragma unroll
        for (int j = 0; j < 8; j++) {
            float v = acc[i][j];
            if (z == 0) v += bias[N0 + tx*8 + j];
            o[j] = (v >= 0.f) ? v : 0.01f * v;
        }
        float* dst = out + (size_t)row * NC + N0 + tx*8;
        *(float4*)(dst)   = *(float4*)(o);
        *(float4*)(dst+4) = *(float4*)(o+4);
    }
}

__device__ __forceinline__ float sigw(float a, float s) {
    float e = __expf(-0.125f * s);
    return __fdividef(a, 1.f + e);
}

// ============================================================
// K2: W[b,h,x,y] = adj*sigmoid(q.k/8), dis = rsqrt(rowsum)
// 128x128 tile per (xt,bh), BK=32 over hd, 256 thr, 8x8 micro
// ============================================================
__global__ __launch_bounds__(256) void k2_att(const float* __restrict__ adj) {
    const int xt = blockIdx.x, bh = blockIdx.y;
    const int b = bh >> 2, h = bh & 3;
    const int x0 = xt * 128;
    __shared__ float qs[32][136];   // [d][x]
    __shared__ float ks[32][136];   // [d][y]
    const int tid = threadIdx.x;
    const int tx = tid & 15, ty = tid >> 4;
    float dsum[8] = {};
    float* Wbase = g_W + (size_t)bh * NN * NN;
    const float* qsrc = g_q + (size_t)b*NN*NC + h*HD;
    const float* ksrc = g_k + (size_t)b*NN*NC + h*HD;
    const float* arow0 = adj + (size_t)b*NN*NN;

    for (int yt = 0; yt < NN/128; yt++) {
        const int y0 = yt * 128;
        float acc[8][8] = {};
        for (int kc = 0; kc < 64; kc += 32) {
            __syncthreads();
            {
                int f = tid & 7;
                #pragma unroll
                for (int p = 0; p < 4; p++) {
                    int r = p*32 + (tid >> 3);
                    float4 v = *(const float4*)(qsrc + (size_t)(x0 + r)*NC + kc + f*4);
                    qs[f*4+0][r] = v.x; qs[f*4+1][r] = v.y;
                    qs[f*4+2][r] = v.z; qs[f*4+3][r] = v.w;
                    float4 w = *(const float4*)(ksrc + (size_t)(y0 + r)*NC + kc + f*4);
                    ks[f*4+0][r] = w.x; ks[f*4+1][r] = w.y;
                    ks[f*4+2][r] = w.z; ks[f*4+3][r] = w.w;
                }
            }
            __syncthreads();
            #pragma unroll 4
            for (int kk = 0; kk < 32; kk++) {
                float a[8], bv[8];
                *(float4*)(a)    = *(const float4*)&qs[kk][ty*8];
                *(float4*)(a+4)  = *(const float4*)&qs[kk][ty*8+4];
                *(float4*)(bv)   = *(const float4*)&ks[kk][tx*8];
                *(float4*)(bv+4) = *(const float4*)&ks[kk][tx*8+4];
                #pragma unroll
                for (int i = 0; i < 8; i++)
                    #pragma unroll
                    for (int j = 0; j < 8; j++) acc[i][j] += a[i] * bv[j];
            }
        }
        // epilogue: sigmoid * adj, store W, accumulate degree
        #pragma unroll
        for (int i = 0; i < 8; i++) {
            int x = x0 + ty*8 + i;
            const float* ar = arow0 + (size_t)x*NN + y0 + tx*8;
            float4 a0 = *(const float4*)(ar);
            float4 a1 = *(const float4*)(ar + 4);
            float4 w0, w1;
            w0.x = sigw(a0.x, acc[i][0]); w0.y = sigw(a0.y, acc[i][1]);
            w0.z = sigw(a0.z, acc[i][2]); w0.w = sigw(a0.w, acc[i][3]);
            w1.x = sigw(a1.x, acc[i][4]); w1.y = sigw(a1.y, acc[i][5]);
            w1.z = sigw(a1.z, acc[i][6]); w1.w = sigw(a1.w, acc[i][7]);
            float* wr = Wbase + (size_t)x*NN + y0 + tx*8;
            *(float4*)(wr)   = w0;
            *(float4*)(wr+4) = w1;
            dsum[i] += ((w0.x + w0.y) + (w0.z + w0.w))
                     + ((w1.x + w1.y) + (w1.z + w1.w));
        }
    }
    #pragma unroll
    for (int i = 0; i < 8; i++) {
        float v = dsum[i];
        #pragma unroll
        for (int o = 8; o; o >>= 1) v += __shfl_xor_sync(0xffffffffu, v, o);
        if (tx == 0)
            g_dis[bh*NN + x0 + ty*8 + i] = (v > 0.f) ? rsqrtf(v) : 0.f;
    }
}

// ============================================================
// K4: Y[b,x,h*64+d] = dis_x * sum_y W[b,h,x,y]*dis_y*X[b,y,h*64+d]
// 128x64 tile per (xt,bh), BK=32 over y, 128 thr, 8x8 micro
// ============================================================
__global__ __launch_bounds__(128) void k4_agg() {
    const int xt = blockIdx.x, bh = blockIdx.y;
    const int b = bh >> 2, h = bh & 3;
    const int x0 = xt * 128;
    __shared__ float Wst[32][136];  // [y][x]
    __shared__ float Xs[32][72];    // [y][d], pre-scaled by dis_y
    const int tid = threadIdx.x;
    const int tx = tid & 7, ty = tid >> 3;
    const float* Wbase = g_W + (size_t)bh * NN * NN;
    const float* disb  = g_dis + bh * NN;
    const float* Xsrc  = g_X + (size_t)b*NN*NC + h*HD;
    float acc[8][8] = {};
    for (int y0 = 0; y0 < NN; y0 += 32) {
        __syncthreads();
        {   // W tile 128x32 -> transposed [y][x]
            int f = tid & 7;
            #pragma unroll
            for (int p = 0; p < 8; p++) {
                int r = p*16 + (tid >> 3);
                float4 v = *(const float4*)(Wbase + (size_t)(x0 + r)*NN + y0 + f*4);
                Wst[f*4+0][r] = v.x; Wst[f*4+1][r] = v.y;
                Wst[f*4+2][r] = v.z; Wst[f*4+3][r] = v.w;
            }
        }
        {   // X tile 32x64, scaled by dis_y
            int r = tid >> 2, c = (tid & 3) * 16;
            float dy = disb[y0 + r];
            const float* src = Xsrc + (size_t)(y0 + r)*NC + c;
            #pragma unroll
            for (int u = 0; u < 4; u++) {
                float4 v = *(const float4*)(src + u*4);
                float4 sv = make_float4(v.x*dy, v.y*dy, v.z*dy, v.w*dy);
                *(float4*)&Xs[r][c + u*4] = sv;
            }
        }
        __syncthreads();
        #pragma unroll 4
        for (int kk = 0; kk < 32; kk++) {
            float a[8], bv[8];
            *(float4*)(a)    = *(const float4*)&Wst[kk][ty*8];
            *(float4*)(a+4)  = *(const float4*)&Wst[kk][ty*8+4];
            *(float4*)(bv)   = *(const float4*)&Xs[kk][tx*8];
            *(float4*)(bv+4) = *(const float4*)&Xs[kk][tx*8+4];
            #pragma unroll
            for (int i = 0; i < 8; i++)
                #pragma unroll
                for (int j = 0; j < 8; j++) acc[i][j] += a[i] * bv[j];
        }
    }
    #pragma unroll
    for (int i = 0; i < 8; i++) {
        int x = x0 + ty*8 + i;
        float dx = disb[x];
        float o[8];
        #pragma unroll
        for (int j = 0; j < 8; j++) o[j] = acc[i][j] * dx;
        float* dst = g_Y + (size_t)(b*NN + x)*NC + h*HD + tx*8;
        *(float4*)(dst)   = *(float4*)(o);
        *(float4*)(dst+4) = *(float4*)(o+4);
    }
}

// ============================================================
// K5: LayerNorm over last dim (256), warp per row
// ============================================================
__global__ __launch_bounds__(256) void k5_ln(const float* __restrict__ g,
                                             const float* __restrict__ bta,
                                             float* __restrict__ out) {
    int gw = (blockIdx.x * 256 + threadIdx.x) >> 5;
    int lane = threadIdx.x & 31;
    if (gw >= NB*NN) return;
    const float* row = g_Y + (size_t)gw * NC;
    float4 v0 = *(const float4*)(row + lane*8);
    float4 v1 = *(const float4*)(row + lane*8 + 4);
    float s  = (v0.x+v0.y) + (v0.z+v0.w) + (v1.x+v1.y) + (v1.z+v1.w);
    float s2 = v0.x*v0.x + v0.y*v0.y + v0.z*v0.z + v0.w*v0.w
             + v1.x*v1.x + v1.y*v1.y + v1.z*v1.z + v1.w*v1.w;
    #pragma unroll
    for (int o = 16; o; o >>= 1) {
        s  += __shfl_xor_sync(0xffffffffu, s,  o);
        s2 += __shfl_xor_sync(0xffffffffu, s2, o);
    }
    float mu  = s * (1.f/NC);
    float var = s2 * (1.f/NC) - mu * mu;
    float inv = rsqrtf(var + 1e-5f);
    int c = lane * 8;
    float4 g0 = *(const float4*)(g + c),   g1 = *(const float4*)(g + c + 4);
    float4 b0 = *(const float4*)(bta + c), b1 = *(const float4*)(bta + c + 4);
    float4 o0, o1;
    o0.x = (v0.x-mu)*inv*g0.x + b0.x;  o0.y = (v0.y-mu)*inv*g0.y + b0.y;
    o0.z = (v0.z-mu)*inv*g0.z + b0.z;  o0.w = (v0.w-mu)*inv*g0.w + b0.w;
    o1.x = (v1.x-mu)*inv*g1.x + b1.x;  o1.y = (v1.y-mu)*inv*g1.y + b1.y;
    o1.z = (v1.z-mu)*inv*g1.z + b1.z;  o1.w = (v1.w-mu)*inv*g1.w + b1.w;
    *(float4*)(out + (size_t)gw*NC + c)     = o0;
    *(float4*)(out + (size_t)gw*NC + c + 4) = o1;
}

extern "C" void kernel_launch(void* const* d_in, const int* in_sizes, int n_in,
                              void* d_out, int out_size) {
    const float* node = (const float*)d_in[0];
    const float* adj  = (const float*)d_in[1];
    const float* Wlin = (const float*)d_in[2];
    const float* blin = (const float*)d_in[3];
    const float* Wq   = (const float*)d_in[4];
    const float* Wk   = (const float*)d_in[5];
    const float* lng  = (const float*)d_in[6];
    const float* lnb  = (const float*)d_in[7];
    float* out = (float*)d_out;

    dim3 g1(NC/128, (NB*NN)/128, 3);        // (2, 64, 3)
    k1_gemm<<<g1, 256>>>(node, Wlin, Wq, Wk, blin);

    dim3 g2(NN/128, NB*NH);                 // (16, 16)
    k2_att<<<g2, 256>>>(adj);

    dim3 g4(NN/128, NB*NH);                 // (16, 16)
    k4_agg<<<g4, 128>>>();

    k5_ln<<<(NB*NN)/8, 256>>>(lng, lnb, out);
}

// round 4
// speedup vs baseline: 2.1050x; 2.0115x over previous
#include <cuda_runtime.h>
#include <cstdint>

#define NB 4
#define NN 2048
#define NC 256
#define NH 4
#define HD 64

// ---- scratch (allocation-free) ----
__device__ float g_X[NB*NN*NC];
__device__ float g_q[NB*NN*NC];
__device__ float g_k[NB*NN*NC];
__device__ float g_Y[NB*NN*NC];
__device__ float g_dis[NB*NH*NN];
__device__ float g_W[(size_t)NB*NH*NN*NN];      // 256MB

__device__ __forceinline__ float to_tf32(float x) {
    uint32_t u;
    asm("cvt.rna.tf32.f32 %0, %1;" : "=r"(u) : "f"(x));
    return __uint_as_float(u);
}
__device__ __forceinline__ void mma_tf32(float c[4], const uint32_t a[4], const uint32_t b[2]) {
    asm volatile(
        "mma.sync.aligned.m16n8k8.row.col.f32.tf32.tf32.f32 "
        "{%0,%1,%2,%3}, {%4,%5,%6,%7}, {%8,%9}, {%0,%1,%2,%3};"
        : "+f"(c[0]), "+f"(c[1]), "+f"(c[2]), "+f"(c[3])
        : "r"(a[0]), "r"(a[1]), "r"(a[2]), "r"(a[3]), "r"(b[0]), "r"(b[1]));
}
__device__ __forceinline__ float sigw(float a, float s) {
    float e = __expf(-0.125f * s);
    return __fdividef(a, 1.f + e);
}

// ============================================================
// K2 (mma.sync tf32): W[b,h,x,y] = adj*sigmoid(q.k/8); dis = rsqrt(rowsum)
// CTA 256 thr, tile 128x128, K=64. smem: qs/ks [128][68] + red[4][128]
// ============================================================
__global__ __launch_bounds__(256) void k2_att_mma(const float* __restrict__ adj) {
    extern __shared__ float sm[];
    float* qs  = sm;                  // 128*68
    float* ks  = sm + 128*68;         // 128*68
    float* red = sm + 2*128*68;       // 4*128
    const int tid = threadIdx.x;
    const int wid = tid >> 5, lid = tid & 31;
    const int grp = lid >> 2, tg = lid & 3;
    const int wm = wid >> 2, wn = wid & 3;
    const int bh = blockIdx.y;
    const int b = bh >> 2, h = bh & 3;
    const int x0 = blockIdx.x * 128;

    {   // stage q (tf32-rounded)
        int f = tid & 15, r0 = tid >> 4;
        const float* src = g_q + ((size_t)(b*NN) + x0)*NC + h*HD;
        #pragma unroll
        for (int p = 0; p < 8; p++) {
            int row = p*16 + r0;
            float4 v = *(const float4*)(src + (size_t)row*NC + f*4);
            float* d = qs + row*68 + f*4;
            d[0]=to_tf32(v.x); d[1]=to_tf32(v.y); d[2]=to_tf32(v.z); d[3]=to_tf32(v.w);
        }
    }
    const float* ksrc  = g_k + (size_t)b*NN*NC + h*HD;
    const float* abase = adj + (size_t)b*NN*NN;
    float*       wbase = g_W + (size_t)bh*NN*NN;
    float dsum[4][2] = {};

    for (int yt = 0; yt < NN/128; yt++) {
        const int y0 = yt * 128;
        __syncthreads();
        {   // stage k tile
            int f = tid & 15, r0 = tid >> 4;
            #pragma unroll
            for (int p = 0; p < 8; p++) {
                int row = p*16 + r0;
                float4 v = *(const float4*)(ksrc + (size_t)(y0+row)*NC + f*4);
                float* d = ks + row*68 + f*4;
                d[0]=to_tf32(v.x); d[1]=to_tf32(v.y); d[2]=to_tf32(v.z); d[3]=to_tf32(v.w);
            }
        }
        __syncthreads();
        float acc[4][4][4] = {};
        #pragma unroll
        for (int kk = 0; kk < 8; kk++) {
            uint32_t a[4][4], bf[4][2];
            #pragma unroll
            for (int i = 0; i < 4; i++) {
                const float* ap = qs + (wm*64 + i*16)*68 + kk*8;
                a[i][0] = __float_as_uint(ap[grp*68 + tg]);
                a[i][1] = __float_as_uint(ap[(grp+8)*68 + tg]);
                a[i][2] = __float_as_uint(ap[grp*68 + tg + 4]);
                a[i][3] = __float_as_uint(ap[(grp+8)*68 + tg + 4]);
            }
            #pragma unroll
            for (int j = 0; j < 4; j++) {
                const float* bp = ks + (wn*32 + j*8 + grp)*68 + kk*8;
                bf[j][0] = __float_as_uint(bp[tg]);
                bf[j][1] = __float_as_uint(bp[tg + 4]);
            }
            #pragma unroll
            for (int i = 0; i < 4; i++)
                #pragma unroll
                for (int j = 0; j < 4; j++)
                    mma_tf32(acc[i][j], a[i], bf[j]);
        }
        // epilogue: sigmoid*adj -> W, accumulate degree
        #pragma unroll
        for (int i = 0; i < 4; i++) {
            #pragma unroll
            for (int u = 0; u < 2; u++) {
                int xr = x0 + wm*64 + i*16 + grp + u*8;
                const float* ar = abase + (size_t)xr*NN + y0 + wn*32 + tg*2;
                float*       wr = wbase + (size_t)xr*NN + y0 + wn*32 + tg*2;
                float lsum = 0.f;
                #pragma unroll
                for (int j = 0; j < 4; j++) {
                    float2 av = *(const float2*)(ar + j*8);
                    float w0 = sigw(av.x, acc[i][j][u*2+0]);
                    float w1 = sigw(av.y, acc[i][j][u*2+1]);
                    *(float2*)(wr + j*8) = make_float2(w0, w1);
                    lsum += w0 + w1;
                }
                dsum[i][u] += lsum;
            }
        }
    }
    // reduce degree: over tg lanes, then over wn warps via smem
    #pragma unroll
    for (int i = 0; i < 4; i++)
        #pragma unroll
        for (int u = 0; u < 2; u++) {
            float v = dsum[i][u];
            v += __shfl_xor_sync(0xffffffffu, v, 1);
            v += __shfl_xor_sync(0xffffffffu, v, 2);
            if (tg == 0) red[wn*128 + wm*64 + i*16 + grp + u*8] = v;
        }
    __syncthreads();
    if (tid < 128) {
        float v = red[tid] + red[128+tid] + red[256+tid] + red[384+tid];
        g_dis[bh*NN + x0 + tid] = (v > 0.f) ? rsqrtf(v) : 0.f;
    }
}

// ============================================================
// K4 (mma.sync tf32): Y[x,d] = dis_x * sum_y W[x,y]*dis_y*X[y,d]
// CTA 256 thr, tile 128x64, K-chunks of 64 over y
// ============================================================
__global__ __launch_bounds__(256) void k4_agg_mma() {
    extern __shared__ float sm[];
    float* Ws = sm;                  // 128*68
    float* Xs = sm + 128*68;         // 64*68
    const int tid = threadIdx.x;
    const int wid = tid >> 5, lid = tid & 31;
    const int grp = lid >> 2, tg = lid & 3;
    const int wm = wid >> 1, wn = wid & 1;
    const int bh = blockIdx.y;
    const int b = bh >> 2, h = bh & 3;
    const int x0 = blockIdx.x * 128;
    const float* wsrc = g_W + (size_t)bh*NN*NN + (size_t)x0*NN;
    const float* xsrc = g_X + (size_t)b*NN*NC + h*HD;
    const float* disb = g_dis + bh*NN;
    float acc[2][4][4] = {};
    for (int y0 = 0; y0 < NN; y0 += 64) {
        __syncthreads();
        {   // Ws: 128 rows x 64 cols, coalesced
            int f = tid & 15, r0 = tid >> 4;
            #pragma unroll
            for (int p = 0; p < 8; p++) {
                int row = p*16 + r0;
                float4 v = *(const float4*)(wsrc + (size_t)row*NN + y0 + f*4);
                float* d = Ws + row*68 + f*4;
                d[0]=to_tf32(v.x); d[1]=to_tf32(v.y); d[2]=to_tf32(v.z); d[3]=to_tf32(v.w);
            }
        }
        {   // Xs[d][y] = tf32(dis_y * X[y,d])
            int y = tid & 63, dblk = (tid >> 6) * 16;
            float dy = disb[y0 + y];
            const float* xr = xsrc + (size_t)(y0+y)*NC + dblk;
            #pragma unroll
            for (int u = 0; u < 4; u++) {
                float4 v = *(const float4*)(xr + u*4);
                Xs[(dblk+u*4+0)*68 + y] = to_tf32(v.x*dy);
                Xs[(dblk+u*4+1)*68 + y] = to_tf32(v.y*dy);
                Xs[(dblk+u*4+2)*68 + y] = to_tf32(v.z*dy);
                Xs[(dblk+u*4+3)*68 + y] = to_tf32(v.w*dy);
            }
        }
        __syncthreads();
        #pragma unroll
        for (int kk = 0; kk < 8; kk++) {
            uint32_t a[2][4], bf[4][2];
            #pragma unroll
            for (int i = 0; i < 2; i++) {
                const float* ap = Ws + (wm*32 + i*16)*68 + kk*8;
                a[i][0] = __float_as_uint(ap[grp*68 + tg]);
                a[i][1] = __float_as_uint(ap[(grp+8)*68 + tg]);
                a[i][2] = __float_as_uint(ap[grp*68 + tg + 4]);
                a[i][3] = __float_as_uint(ap[(grp+8)*68 + tg + 4]);
            }
            #pragma unroll
            for (int j = 0; j < 4; j++) {
                const float* bp = Xs + (wn*32 + j*8 + grp)*68 + kk*8;
                bf[j][0] = __float_as_uint(bp[tg]);
                bf[j][1] = __float_as_uint(bp[tg + 4]);
            }
            #pragma unroll
            for (int i = 0; i < 2; i++)
                #pragma unroll
                for (int j = 0; j < 4; j++)
                    mma_tf32(acc[i][j], a[i], bf[j]);
        }
    }
    #pragma unroll
    for (int i = 0; i < 2; i++) {
        #pragma unroll
        for (int u = 0; u < 2; u++) {
            int x = x0 + wm*32 + i*16 + grp + u*8;
            float dx = disb[x];
            float* dst = g_Y + (size_t)(b*NN + x)*NC + h*HD + wn*32 + tg*2;
            #pragma unroll
            for (int j = 0; j < 4; j++)
                *(float2*)(dst + j*8) = make_float2(acc[i][j][u*2]*dx, acc[i][j][u*2+1]*dx);
        }
    }
}

// ============================================================
// K1: out = lrelu(A[8192,256] @ W[256,256] (+bias))  (fp32)
// ============================================================
__global__ __launch_bounds__(256) void k1_gemm(const float* __restrict__ A,
                                               const float* __restrict__ W0,
                                               const float* __restrict__ W1,
                                               const float* __restrict__ W2,
                                               const float* __restrict__ bias) {
    const int z = blockIdx.z;
    const float* Wm = (z == 0) ? W0 : ((z == 1) ? W1 : W2);
    float* out = (z == 0) ? g_X : ((z == 1) ? g_q : g_k);
    __shared__ float As[16][136];
    __shared__ float Bs[16][136];
    const int tid = threadIdx.x;
    const int tx = tid & 15, ty = tid >> 4;
    const int M0 = blockIdx.y * 128, N0 = blockIdx.x * 128;
    float acc[8][8] = {};
    for (int k0 = 0; k0 < 256; k0 += 16) {
        __syncthreads();
        {
            int f = tid & 3;
            #pragma unroll
            for (int p = 0; p < 2; p++) {
                int r = p*64 + (tid >> 2);
                float4 v = *(const float4*)(A + (size_t)(M0 + r)*NC + k0 + f*4);
                As[f*4+0][r] = v.x; As[f*4+1][r] = v.y;
                As[f*4+2][r] = v.z; As[f*4+3][r] = v.w;
            }
        }
        {
            int r = tid >> 4, c = (tid & 15) * 8;
            const float* src = Wm + (size_t)(k0 + r)*NC + N0 + c;
            *(float4*)&Bs[r][c]   = *(const float4*)(src);
            *(float4*)&Bs[r][c+4] = *(const float4*)(src + 4);
        }
        __syncthreads();
        #pragma unroll
        for (int kk = 0; kk < 16; kk++) {
            float a[8], bv[8];
            *(float4*)(a)    = *(const float4*)&As[kk][ty*8];
            *(float4*)(a+4)  = *(const float4*)&As[kk][ty*8+4];
            *(float4*)(bv)   = *(const float4*)&Bs[kk][tx*8];
            *(float4*)(bv+4) = *(const float4*)&Bs[kk][tx*8+4];
            #pragma unroll
            for (int i = 0; i < 8; i++)
                #pragma unroll
                for (int j = 0; j < 8; j++) acc[i][j] += a[i] * bv[j];
        }
    }
    #pragma unroll
    for (int i = 0; i < 8; i++) {
        int row = M0 + ty*8 + i;
        float o[8];
        #pragma unroll
        for (int j = 0; j < 8; j++) {
            float v = acc[i][j];
            if (z == 0) v += bias[N0 + tx*8 + j];
            o[j] = (v >= 0.f) ? v : 0.01f * v;
        }
        float* dst = out + (size_t)row * NC + N0 + tx*8;
        *(float4*)(dst)   = *(float4*)(o);
        *(float4*)(dst+4) = *(float4*)(o+4);
    }
}

// ============================================================
// K5: LayerNorm over last dim (256), warp per row
// ============================================================
__global__ __launch_bounds__(256) void k5_ln(const float* __restrict__ g,
                                             const float* __restrict__ bta,
                                             float* __restrict__ out) {
    int gw = (blockIdx.x * 256 + threadIdx.x) >> 5;
    int lane = threadIdx.x & 31;
    if (gw >= NB*NN) return;
    const float* row = g_Y + (size_t)gw * NC;
    float4 v0 = *(const float4*)(row + lane*8);
    float4 v1 = *(const float4*)(row + lane*8 + 4);
    float s  = (v0.x+v0.y) + (v0.z+v0.w) + (v1.x+v1.y) + (v1.z+v1.w);
    float s2 = v0.x*v0.x + v0.y*v0.y + v0.z*v0.z + v0.w*v0.w
             + v1.x*v1.x + v1.y*v1.y + v1.z*v1.z + v1.w*v1.w;
    #pragma unroll
    for (int o = 16; o; o >>= 1) {
        s  += __shfl_xor_sync(0xffffffffu, s,  o);
        s2 += __shfl_xor_sync(0xffffffffu, s2, o);
    }
    float mu  = s * (1.f/NC);
    float var = s2 * (1.f/NC) - mu * mu;
    float inv = rsqrtf(var + 1e-5f);
    int c = lane * 8;
    float4 g0 = *(const float4*)(g + c),   g1 = *(const float4*)(g + c + 4);
    float4 b0 = *(const float4*)(bta + c), b1 = *(const float4*)(bta + c + 4);
    float4 o0, o1;
    o0.x = (v0.x-mu)*inv*g0.x + b0.x;  o0.y = (v0.y-mu)*inv*g0.y + b0.y;
    o0.z = (v0.z-mu)*inv*g0.z + b0.z;  o0.w = (v0.w-mu)*inv*g0.w + b0.w;
    o1.x = (v1.x-mu)*inv*g1.x + b1.x;  o1.y = (v1.y-mu)*inv*g1.y + b1.y;
    o1.z = (v1.z-mu)*inv*g1.z + b1.z;  o1.w = (v1.w-mu)*inv*g1.w + b1.w;
    *(float4*)(out + (size_t)gw*NC + c)     = o0;
    *(float4*)(out + (size_t)gw*NC + c + 4) = o1;
}

extern "C" void kernel_launch(void* const* d_in, const int* in_sizes, int n_in,
                              void* d_out, int out_size) {
    const float* node = (const float*)d_in[0];
    const float* adj  = (const float*)d_in[1];
    const float* Wlin = (const float*)d_in[2];
    const float* blin = (const float*)d_in[3];
    const float* Wq   = (const float*)d_in[4];
    const float* Wk   = (const float*)d_in[5];
    const float* lng  = (const float*)d_in[6];
    const float* lnb  = (const float*)d_in[7];
    float* out = (float*)d_out;

    const int smem_k2 = (2*128*68 + 4*128) * 4;     // 71,680 B
    const int smem_k4 = (128*68 + 64*68) * 4;       // 52,224 B
    cudaFuncSetAttribute(k2_att_mma, cudaFuncAttributeMaxDynamicSharedMemorySize, smem_k2);
    cudaFuncSetAttribute(k4_agg_mma, cudaFuncAttributeMaxDynamicSharedMemorySize, smem_k4);

    dim3 g1(NC/128, (NB*NN)/128, 3);
    k1_gemm<<<g1, 256>>>(node, Wlin, Wq, Wk, blin);

    dim3 g2(NN/128, NB*NH);
    k2_att_mma<<<g2, 256, smem_k2>>>(adj);

    dim3 g4(NN/128, NB*NH);
    k4_agg_mma<<<g4, 256, smem_k4>>>();

    k5_ln<<<(NB*NN)/8, 256>>>(lng, lnb, out);
}